// round 11
// baseline (speedup 1.0000x reference)
#include <cuda_runtime.h>
#include <cuda_bf16.h>
#include <cstdint>

// CartesianToDihedral: (1024, 2048, 3, 3) f32 -> (angles (1024,12282), first_three (1024,9))
// PERSISTENT kernel: one wave (1184 blocks), grid-stride over 6144 tiles.
// Body = R9: W=4 windows/thread, 3x LDG.128 owned floats, edge shuffles
// (E4=E0', E5=E1', p4=p0'), lane-31 hoisted overlap loads, __stcs stores,
// third cross eliminated: yc = (n1 x u).n2 == -e0.n2.

namespace {
constexpr int B_SZ        = 1024;
constexpr int PTS_PER_ROW = 6144;                 // 2048*3
constexpr int FLT_PER_ROW = PTS_PER_ROW * 3;      // 18432
constexpr int NWIN        = PTS_PER_ROW - 3;      // 6141
constexpr int OUT_STRIDE  = 2 * NWIN;             // 12282
constexpr int W           = 4;                    // windows per thread
constexpr int TPB         = 256;
constexpr int WIN_PER_BLK = W * TPB;              // 1024
constexpr int CHUNKS      = 6;                    // 6*1024 = 6144 >= 6141
constexpr int NTILES      = B_SZ * CHUNKS;        // 6144
constexpr int GRID        = 148 * 8;              // one full wave (8 CTAs/SM @ 32 regs)
constexpr long long TOTAL_IN = (long long)B_SZ * FLT_PER_ROW;  // 18,874,368
}

__device__ __forceinline__ void dihedral_core(
    float e0x, float e0y, float e0z,
    float e1x, float e1y, float e1z,
    float e2x, float e2y, float e2z,
    float& sv, float& cv)
{
    // u = normalize(e1 + 1e-8)
    const float ux0 = e1x + 1e-8f;
    const float uy0 = e1y + 1e-8f;
    const float uz0 = e1z + 1e-8f;
    const float rin = rsqrtf(fmaf(ux0, ux0, fmaf(uy0, uy0, uz0 * uz0)));
    const float ux = ux0 * rin, uy = uy0 * rin, uz = uz0 * rin;

    // n1 = cross(e0, u)
    const float n1x = fmaf(e0y, uz, -e0z * uy);
    const float n1y = fmaf(e0z, ux, -e0x * uz);
    const float n1z = fmaf(e0x, uy, -e0y * ux);
    // n2 = cross(u, e2)
    const float n2x = fmaf(uy, e2z, -uz * e2y);
    const float n2y = fmaf(uz, e2x, -ux * e2z);
    const float n2z = fmaf(ux, e2y, -uy * e2x);

    // xc = n1.n2 + 1e-8 ; yc = (n1 x u).n2 == -e0.n2  (u.n2 == 0, |u| = 1)
    const float xc = fmaf(n1x, n2x, fmaf(n1y, n2y, fmaf(n1z, n2z, 1e-8f)));
    const float yc = -fmaf(e0x, n2x, fmaf(e0y, n2y, e0z * n2z));

    const float r2 = fmaf(xc, xc, yc * yc);
    const float ri = rsqrtf(r2);
    sv = (r2 > 0.0f) ? yc * ri : 0.0f;   // atan2(0,0)=0
    cv = (r2 > 0.0f) ? xc * ri : 1.0f;
}

__global__ __launch_bounds__(TPB)
void dihedral_kernel(const float* __restrict__ in, float* __restrict__ out) {
    const int lane = threadIdx.x & 31;
    const bool last = (lane == 31);

    for (int tile = blockIdx.x; tile < NTILES; tile += GRID) {
        const int batch = tile / CHUNKS;
        const int chunk = tile - batch * CHUNKS;
        const int gw0   = chunk * WIN_PER_BLK + threadIdx.x * W;

        const long long rowBase = (long long)batch * FLT_PER_ROW;
        const long long fbase   = rowBase + (long long)gw0 * 3;   // mult of 12 -> 16B aligned

        // ── Owned floats f[0..11]: 3 aligned LDG.128. Always in bounds.
        float f[12];
        {
            const float4* p4p = reinterpret_cast<const float4*>(in + fbase);
            const float4 v0 = p4p[0], v1 = p4p[1], v2 = p4p[2];
            f[0]=v0.x; f[1]=v0.y; f[2]=v0.z;  f[3]=v0.w;
            f[4]=v1.x; f[5]=v1.y; f[6]=v1.z;  f[7]=v1.w;
            f[8]=v2.x; f[9]=v2.y; f[10]=v2.z; f[11]=v2.w;
        }

        // ── Hoisted predicated overlap loads (lane 31 only).
        float g[9];
        if (last) {
            const long long gbase = fbase + 12;          // 16B aligned
            if (gbase + 9 <= TOTAL_IN) {                 // false only at global tail
                const float4 v0 = *reinterpret_cast<const float4*>(in + gbase);
                const float4 v1 = *reinterpret_cast<const float4*>(in + gbase + 4);
                g[0]=v0.x; g[1]=v0.y; g[2]=v0.z; g[3]=v0.w;
                g[4]=v1.x; g[5]=v1.y; g[6]=v1.z; g[7]=v1.w;
                g[8] = in[gbase + 8];
            } else {
                #pragma unroll
                for (int j = 0; j < 9; j++)
                    g[j] = (gbase + j < TOTAL_IN) ? in[gbase + j] : 0.0f;
            }
        }

        // ── Owned edges E_j = p_j - p_{j+1}, j = 0..2.
        const float E0x = f[0]-f[3],  E0y = f[1]-f[4],  E0z = f[2]-f[5];
        const float E1x = f[3]-f[6],  E1y = f[4]-f[7],  E1z = f[5]-f[8];
        const float E2x = f[6]-f[9],  E2y = f[7]-f[10], E2z = f[8]-f[11];

        // ── Neighbor data via shuffle: p4 = p0'; E4 = E0'; E5 = E1'.
        float p4x = __shfl_down_sync(0xFFFFFFFFu, f[0], 1);
        float p4y = __shfl_down_sync(0xFFFFFFFFu, f[1], 1);
        float p4z = __shfl_down_sync(0xFFFFFFFFu, f[2], 1);
        float E4x = __shfl_down_sync(0xFFFFFFFFu, E0x, 1);
        float E4y = __shfl_down_sync(0xFFFFFFFFu, E0y, 1);
        float E4z = __shfl_down_sync(0xFFFFFFFFu, E0z, 1);
        float E5x = __shfl_down_sync(0xFFFFFFFFu, E1x, 1);
        float E5y = __shfl_down_sync(0xFFFFFFFFu, E1y, 1);
        float E5z = __shfl_down_sync(0xFFFFFFFFu, E1z, 1);
        if (last) {
            p4x = g[0]; p4y = g[1]; p4z = g[2];
            E4x = g[0]-g[3]; E4y = g[1]-g[4]; E4z = g[2]-g[5];
            E5x = g[3]-g[6]; E5y = g[4]-g[7]; E5z = g[5]-g[8];
        }
        const float E3x = f[9]-p4x, E3y = f[10]-p4y, E3z = f[11]-p4z;

        float sv[W], cv[W];
        dihedral_core(E0x,E0y,E0z, E1x,E1y,E1z, E2x,E2y,E2z, sv[0], cv[0]);
        dihedral_core(E1x,E1y,E1z, E2x,E2y,E2z, E3x,E3y,E3z, sv[1], cv[1]);
        dihedral_core(E2x,E2y,E2z, E3x,E3y,E3z, E4x,E4y,E4z, sv[2], cv[2]);
        dihedral_core(E3x,E3y,E3z, E4x,E4y,E4z, E5x,E5y,E5z, sv[3], cv[3]);

        const long long ob = (long long)batch * OUT_STRIDE;

        if (gw0 + W <= NWIN) {
            float2* s2 = reinterpret_cast<float2*>(out + ob + gw0);
            __stcs(s2 + 0, make_float2(sv[0], sv[1]));
            __stcs(s2 + 1, make_float2(sv[2], sv[3]));
            float* cp = out + ob + NWIN + gw0;
            __stcs(cp + 0, cv[0]); __stcs(cp + 1, cv[1]);
            __stcs(cp + 2, cv[2]); __stcs(cp + 3, cv[3]);
        } else {
            #pragma unroll
            for (int w = 0; w < W; w++) {
                if (gw0 + w < NWIN) {
                    __stcs(out + ob + gw0 + w,        sv[w]);
                    __stcs(out + ob + NWIN + gw0 + w, cv[w]);
                }
            }
        }

        // first_three: 9 floats per batch appended after all angle rows.
        if (chunk == 0 && threadIdx.x < 9) {
            out[(long long)B_SZ * OUT_STRIDE + (long long)batch * 9 + threadIdx.x] =
                in[rowBase + threadIdx.x];
        }
    }
}

extern "C" void kernel_launch(void* const* d_in, const int* in_sizes, int n_in,
                              void* d_out, int out_size) {
    const float* in = (const float*)d_in[0];
    float* out = (float*)d_out;
    dihedral_kernel<<<GRID, TPB>>>(in, out);
}

// round 12
// speedup vs baseline: 1.0026x; 1.0026x over previous
#include <cuda_runtime.h>
#include <cuda_bf16.h>
#include <cstdint>

// CartesianToDihedral: (1024, 2048, 3, 3) f32 -> (angles (1024,12282), first_three (1024,9))
// R9 frame (W=4, 3x LDG.128 owned floats, edge shuffles, lane-31 hoisted overlap,
// __stcs stores, yc = -e0.n2) with the dihedral math executed 2-wide via
// packed f32x2 PTX (fma/mul/add.rn.f32x2 -> FFMA2/FMUL2/FADD2).

namespace {
constexpr int B_SZ        = 1024;
constexpr int PTS_PER_ROW = 6144;                 // 2048*3
constexpr int FLT_PER_ROW = PTS_PER_ROW * 3;      // 18432
constexpr int NWIN        = PTS_PER_ROW - 3;      // 6141
constexpr int OUT_STRIDE  = 2 * NWIN;             // 12282
constexpr int W           = 4;                    // windows per thread
constexpr int TPB         = 256;
constexpr int WIN_PER_BLK = W * TPB;              // 1024
constexpr int CHUNKS      = 6;                    // 6*1024 = 6144 >= 6141
constexpr long long TOTAL_IN = (long long)B_SZ * FLT_PER_ROW;  // 18,874,368
}

// ── f32x2 packed helpers ─────────────────────────────────────────────
__device__ __forceinline__ uint64_t pk2(float lo, float hi) {
    uint64_t r; asm("mov.b64 %0, {%1, %2};" : "=l"(r) : "f"(lo), "f"(hi)); return r;
}
__device__ __forceinline__ void upk2(float& lo, float& hi, uint64_t v) {
    asm("mov.b64 {%0, %1}, %2;" : "=f"(lo), "=f"(hi) : "l"(v));
}
__device__ __forceinline__ uint64_t mul2(uint64_t a, uint64_t b) {
    uint64_t d; asm("mul.rn.f32x2 %0, %1, %2;" : "=l"(d) : "l"(a), "l"(b)); return d;
}
__device__ __forceinline__ uint64_t add2(uint64_t a, uint64_t b) {
    uint64_t d; asm("add.rn.f32x2 %0, %1, %2;" : "=l"(d) : "l"(a), "l"(b)); return d;
}
__device__ __forceinline__ uint64_t fma2(uint64_t a, uint64_t b, uint64_t c) {
    uint64_t d; asm("fma.rn.f32x2 %0, %1, %2, %3;" : "=l"(d) : "l"(a), "l"(b), "l"(c)); return d;
}

// Two windows at once: e0/e1/e2 packed {window_lo, window_hi}.
__device__ __forceinline__ void dihedral_pair(
    uint64_t e0x, uint64_t e0y, uint64_t e0z,
    uint64_t e1x, uint64_t e1y, uint64_t e1z,
    uint64_t e2x, uint64_t e2y, uint64_t e2z,
    float& sv0, float& cv0, float& sv1, float& cv1)
{
    const uint64_t EPS8 = pk2(1e-8f, 1e-8f);
    const uint64_t NEG1 = pk2(-1.0f, -1.0f);

    // u = normalize(e1 + 1e-8)
    const uint64_t ux0 = add2(e1x, EPS8);
    const uint64_t uy0 = add2(e1y, EPS8);
    const uint64_t uz0 = add2(e1z, EPS8);
    const uint64_t nn  = fma2(ux0, ux0, fma2(uy0, uy0, mul2(uz0, uz0)));
    float na, nb; upk2(na, nb, nn);
    const uint64_t rin = pk2(rsqrtf(na), rsqrtf(nb));
    const uint64_t ux = mul2(ux0, rin), uy = mul2(uy0, rin), uz = mul2(uz0, rin);

    // n1 = cross(e0, u):  s - t  via fma(t, -1, s)
    const uint64_t n1x = fma2(mul2(e0z, uy), NEG1, mul2(e0y, uz));
    const uint64_t n1y = fma2(mul2(e0x, uz), NEG1, mul2(e0z, ux));
    const uint64_t n1z = fma2(mul2(e0y, ux), NEG1, mul2(e0x, uy));
    // n2 = cross(u, e2)
    const uint64_t n2x = fma2(mul2(uz, e2y), NEG1, mul2(uy, e2z));
    const uint64_t n2y = fma2(mul2(ux, e2z), NEG1, mul2(uz, e2x));
    const uint64_t n2z = fma2(mul2(uy, e2x), NEG1, mul2(ux, e2y));

    // xc = n1.n2 + 1e-8 ;  d = e0.n2  (yc = -d)
    const uint64_t xc = fma2(n1x, n2x, fma2(n1y, n2y, fma2(n1z, n2z, EPS8)));
    const uint64_t dd = fma2(e0x, n2x, fma2(e0y, n2y, mul2(e0z, n2z)));
    const uint64_t r2 = fma2(xc, xc, mul2(dd, dd));   // == xc^2 + yc^2

    float xa, xb, da, db, ra, rb;
    upk2(xa, xb, xc); upk2(da, db, dd); upk2(ra, rb, r2);

    const float ria = rsqrtf(ra);
    const float rib = rsqrtf(rb);
    sv0 = (ra > 0.0f) ? -da * ria : 0.0f;   // atan2(0,0)=0
    cv0 = (ra > 0.0f) ?  xa * ria : 1.0f;
    sv1 = (rb > 0.0f) ? -db * rib : 0.0f;
    cv1 = (rb > 0.0f) ?  xb * rib : 1.0f;
}

__global__ __launch_bounds__(TPB)
void dihedral_kernel(const float* __restrict__ in, float* __restrict__ out) {
    const int bid   = blockIdx.x;
    const int batch = bid / CHUNKS;
    const int chunk = bid - batch * CHUNKS;
    const int lane  = threadIdx.x & 31;
    const bool last = (lane == 31);
    const int gw0   = chunk * WIN_PER_BLK + threadIdx.x * W;

    const long long rowBase = (long long)batch * FLT_PER_ROW;
    const long long fbase   = rowBase + (long long)gw0 * 3;   // mult of 12 -> 16B aligned

    // ── Owned floats f[0..11]: 3 aligned LDG.128. Always in bounds.
    float f[12];
    {
        const float4* p4p = reinterpret_cast<const float4*>(in + fbase);
        const float4 v0 = p4p[0], v1 = p4p[1], v2 = p4p[2];
        f[0]=v0.x; f[1]=v0.y; f[2]=v0.z;  f[3]=v0.w;
        f[4]=v1.x; f[5]=v1.y; f[6]=v1.z;  f[7]=v1.w;
        f[8]=v2.x; f[9]=v2.y; f[10]=v2.z; f[11]=v2.w;
    }

    // ── Hoisted predicated overlap loads (lane 31 only).
    float g[9];
    if (last) {
        const long long gbase = fbase + 12;          // 16B aligned
        if (gbase + 9 <= TOTAL_IN) {                 // false only at global tail
            const float4 v0 = *reinterpret_cast<const float4*>(in + gbase);
            const float4 v1 = *reinterpret_cast<const float4*>(in + gbase + 4);
            g[0]=v0.x; g[1]=v0.y; g[2]=v0.z; g[3]=v0.w;
            g[4]=v1.x; g[5]=v1.y; g[6]=v1.z; g[7]=v1.w;
            g[8] = in[gbase + 8];
        } else {
            #pragma unroll
            for (int j = 0; j < 9; j++)
                g[j] = (gbase + j < TOTAL_IN) ? in[gbase + j] : 0.0f;
        }
    }

    // ── Owned edges E_j = p_j - p_{j+1}, j = 0..2.
    const float E0x = f[0]-f[3],  E0y = f[1]-f[4],  E0z = f[2]-f[5];
    const float E1x = f[3]-f[6],  E1y = f[4]-f[7],  E1z = f[5]-f[8];
    const float E2x = f[6]-f[9],  E2y = f[7]-f[10], E2z = f[8]-f[11];

    // ── Neighbor data via shuffle: p4 = p0'; E4 = E0'; E5 = E1'.
    float p4x = __shfl_down_sync(0xFFFFFFFFu, f[0], 1);
    float p4y = __shfl_down_sync(0xFFFFFFFFu, f[1], 1);
    float p4z = __shfl_down_sync(0xFFFFFFFFu, f[2], 1);
    float E4x = __shfl_down_sync(0xFFFFFFFFu, E0x, 1);
    float E4y = __shfl_down_sync(0xFFFFFFFFu, E0y, 1);
    float E4z = __shfl_down_sync(0xFFFFFFFFu, E0z, 1);
    float E5x = __shfl_down_sync(0xFFFFFFFFu, E1x, 1);
    float E5y = __shfl_down_sync(0xFFFFFFFFu, E1y, 1);
    float E5z = __shfl_down_sync(0xFFFFFFFFu, E1z, 1);
    if (last) {
        p4x = g[0]; p4y = g[1]; p4z = g[2];
        E4x = g[0]-g[3]; E4y = g[1]-g[4]; E4z = g[2]-g[5];
        E5x = g[3]-g[6]; E5y = g[4]-g[7]; E5z = g[5]-g[8];
    }
    const float E3x = f[9]-p4x, E3y = f[10]-p4y, E3z = f[11]-p4z;

    // ── Pack window pairs: A = windows (0,1), B = windows (2,3).
    // A: e0=(E0,E1) e1=(E1,E2) e2=(E2,E3);  B: e0=(E2,E3) e1=(E3,E4) e2=(E4,E5).
    const uint64_t A0x = pk2(E0x,E1x), A0y = pk2(E0y,E1y), A0z = pk2(E0z,E1z);
    const uint64_t A1x = pk2(E1x,E2x), A1y = pk2(E1y,E2y), A1z = pk2(E1z,E2z);
    const uint64_t S23x = pk2(E2x,E3x), S23y = pk2(E2y,E3y), S23z = pk2(E2z,E3z); // A.e2 == B.e0
    const uint64_t B1x = pk2(E3x,E4x), B1y = pk2(E3y,E4y), B1z = pk2(E3z,E4z);
    const uint64_t B2x = pk2(E4x,E5x), B2y = pk2(E4y,E5y), B2z = pk2(E4z,E5z);

    float sv[W], cv[W];
    dihedral_pair(A0x,A0y,A0z, A1x,A1y,A1z, S23x,S23y,S23z, sv[0],cv[0], sv[1],cv[1]);
    dihedral_pair(S23x,S23y,S23z, B1x,B1y,B1z, B2x,B2y,B2z, sv[2],cv[2], sv[3],cv[3]);

    const long long ob = (long long)batch * OUT_STRIDE;

    if (gw0 + W <= NWIN) {
        float2* s2 = reinterpret_cast<float2*>(out + ob + gw0);
        __stcs(s2 + 0, make_float2(sv[0], sv[1]));
        __stcs(s2 + 1, make_float2(sv[2], sv[3]));
        float* cp = out + ob + NWIN + gw0;
        __stcs(cp + 0, cv[0]); __stcs(cp + 1, cv[1]);
        __stcs(cp + 2, cv[2]); __stcs(cp + 3, cv[3]);
    } else {
        #pragma unroll
        for (int w = 0; w < W; w++) {
            if (gw0 + w < NWIN) {
                __stcs(out + ob + gw0 + w,        sv[w]);
                __stcs(out + ob + NWIN + gw0 + w, cv[w]);
            }
        }
    }

    // first_three: 9 floats per batch appended after all angle rows.
    if (chunk == 0 && threadIdx.x < 9) {
        out[(long long)B_SZ * OUT_STRIDE + (long long)batch * 9 + threadIdx.x] =
            in[rowBase + threadIdx.x];
    }
}

extern "C" void kernel_launch(void* const* d_in, const int* in_sizes, int n_in,
                              void* d_out, int out_size) {
    const float* in = (const float*)d_in[0];
    float* out = (float*)d_out;
    dihedral_kernel<<<B_SZ * CHUNKS, TPB>>>(in, out);
}

// round 16
// speedup vs baseline: 1.0710x; 1.0683x over previous
#include <cuda_runtime.h>
#include <cuda_bf16.h>
#include <cstdint>

// CartesianToDihedral: (1024, 2048, 3, 3) f32 -> (angles (1024,12282), first_three (1024,9))
// R9 frame: W=4, 3x LDG.128 owned floats, edge shuffles (E4=E0', E5=E1', p4=p0'),
// lane-31 hoisted overlap loads, __stcs stores.
// NEW: scale-invariant core — no normalize. With b = e1+eps, s = b.b, L = sqrt(s):
//   atan2(yc, xc) == atan2(-L*(e0 . (b x e2)), (e0 x b).(b x e2) + 1e-8*s)   (exact)
// sqrt(s) runs in parallel with the crosses; selects eliminated (s > 0 always).

namespace {
constexpr int B_SZ        = 1024;
constexpr int PTS_PER_ROW = 6144;                 // 2048*3
constexpr int FLT_PER_ROW = PTS_PER_ROW * 3;      // 18432
constexpr int NWIN        = PTS_PER_ROW - 3;      // 6141
constexpr int OUT_STRIDE  = 2 * NWIN;             // 12282
constexpr int W           = 4;                    // windows per thread
constexpr int TPB         = 256;
constexpr int WIN_PER_BLK = W * TPB;              // 1024
constexpr int CHUNKS      = 6;                    // 6*1024 = 6144 >= 6141
constexpr long long TOTAL_IN = (long long)B_SZ * FLT_PER_ROW;  // 18,874,368
}

__device__ __forceinline__ void dihedral_core(
    float e0x, float e0y, float e0z,
    float e1x, float e1y, float e1z,
    float e2x, float e2y, float e2z,
    float& sv, float& cv)
{
    // b = e1 + 1e-8 (unnormalized)
    const float bx = e1x + 1e-8f;
    const float by = e1y + 1e-8f;
    const float bz = e1z + 1e-8f;
    const float s  = fmaf(bx, bx, fmaf(by, by, bz * bz));   // |b|^2 > 0

    // n1 = cross(e0, b)
    const float n1x = fmaf(e0y, bz, -e0z * by);
    const float n1y = fmaf(e0z, bx, -e0x * bz);
    const float n1z = fmaf(e0x, by, -e0y * bx);
    // n2 = cross(b, e2)
    const float n2x = fmaf(by, e2z, -bz * e2y);
    const float n2y = fmaf(bz, e2x, -bx * e2z);
    const float n2z = fmaf(bx, e2y, -by * e2x);

    // xc = n1.n2 + 1e-8*s  (== s^2 * (n1_hat.n2_hat + 1e-8) / ... scale-invariant)
    const float xc = fmaf(n1x, n2x, fmaf(n1y, n2y, fmaf(n1z, n2z, 1e-8f * s)));
    // yc = -L * (e0.n2)   (L = sqrt(s) computed in parallel with crosses/dots)
    const float d  = fmaf(e0x, n2x, fmaf(e0y, n2y, e0z * n2z));
    const float t  = -sqrtf(s) * d;

    const float r2 = fmaf(xc, xc, t * t);   // > 0 always (xc >= 1e-8*s when dots vanish)
    const float ri = rsqrtf(r2);
    sv = t * ri;
    cv = xc * ri;
}

__global__ __launch_bounds__(TPB)
void dihedral_kernel(const float* __restrict__ in, float* __restrict__ out) {
    const int bid   = blockIdx.x;
    const int batch = bid / CHUNKS;
    const int chunk = bid - batch * CHUNKS;
    const int lane  = threadIdx.x & 31;
    const bool last = (lane == 31);
    const int gw0   = chunk * WIN_PER_BLK + threadIdx.x * W;

    const long long rowBase = (long long)batch * FLT_PER_ROW;
    const long long fbase   = rowBase + (long long)gw0 * 3;   // mult of 12 -> 16B aligned

    // ── Owned floats f[0..11]: 3 aligned LDG.128. Always in bounds.
    float f[12];
    {
        const float4* p4p = reinterpret_cast<const float4*>(in + fbase);
        const float4 v0 = p4p[0], v1 = p4p[1], v2 = p4p[2];
        f[0]=v0.x; f[1]=v0.y; f[2]=v0.z;  f[3]=v0.w;
        f[4]=v1.x; f[5]=v1.y; f[6]=v1.z;  f[7]=v1.w;
        f[8]=v2.x; f[9]=v2.y; f[10]=v2.z; f[11]=v2.w;
    }

    // ── Hoisted predicated overlap loads (lane 31 only).
    float g[9];
    if (last) {
        const long long gbase = fbase + 12;          // 16B aligned
        if (gbase + 9 <= TOTAL_IN) {                 // false only at global tail
            const float4 v0 = *reinterpret_cast<const float4*>(in + gbase);
            const float4 v1 = *reinterpret_cast<const float4*>(in + gbase + 4);
            g[0]=v0.x; g[1]=v0.y; g[2]=v0.z; g[3]=v0.w;
            g[4]=v1.x; g[5]=v1.y; g[6]=v1.z; g[7]=v1.w;
            g[8] = in[gbase + 8];
        } else {
            #pragma unroll
            for (int j = 0; j < 9; j++)
                g[j] = (gbase + j < TOTAL_IN) ? in[gbase + j] : 0.0f;
        }
    }

    // ── Owned edges E_j = p_j - p_{j+1}, j = 0..2.
    const float E0x = f[0]-f[3],  E0y = f[1]-f[4],  E0z = f[2]-f[5];
    const float E1x = f[3]-f[6],  E1y = f[4]-f[7],  E1z = f[5]-f[8];
    const float E2x = f[6]-f[9],  E2y = f[7]-f[10], E2z = f[8]-f[11];

    // ── Neighbor data via shuffle: p4 = p0'; E4 = E0'; E5 = E1'.
    float p4x = __shfl_down_sync(0xFFFFFFFFu, f[0], 1);
    float p4y = __shfl_down_sync(0xFFFFFFFFu, f[1], 1);
    float p4z = __shfl_down_sync(0xFFFFFFFFu, f[2], 1);
    float E4x = __shfl_down_sync(0xFFFFFFFFu, E0x, 1);
    float E4y = __shfl_down_sync(0xFFFFFFFFu, E0y, 1);
    float E4z = __shfl_down_sync(0xFFFFFFFFu, E0z, 1);
    float E5x = __shfl_down_sync(0xFFFFFFFFu, E1x, 1);
    float E5y = __shfl_down_sync(0xFFFFFFFFu, E1y, 1);
    float E5z = __shfl_down_sync(0xFFFFFFFFu, E1z, 1);
    if (last) {
        p4x = g[0]; p4y = g[1]; p4z = g[2];
        E4x = g[0]-g[3]; E4y = g[1]-g[4]; E4z = g[2]-g[5];
        E5x = g[3]-g[6]; E5y = g[4]-g[7]; E5z = g[5]-g[8];
    }
    const float E3x = f[9]-p4x, E3y = f[10]-p4y, E3z = f[11]-p4z;

    float sv[W], cv[W];
    dihedral_core(E0x,E0y,E0z, E1x,E1y,E1z, E2x,E2y,E2z, sv[0], cv[0]);
    dihedral_core(E1x,E1y,E1z, E2x,E2y,E2z, E3x,E3y,E3z, sv[1], cv[1]);
    dihedral_core(E2x,E2y,E2z, E3x,E3y,E3z, E4x,E4y,E4z, sv[2], cv[2]);
    dihedral_core(E3x,E3y,E3z, E4x,E4y,E4z, E5x,E5y,E5z, sv[3], cv[3]);

    const long long ob = (long long)batch * OUT_STRIDE;

    if (gw0 + W <= NWIN) {
        // sin: (ob+gw0) even -> 8B-aligned float2 streaming stores
        float2* s2 = reinterpret_cast<float2*>(out + ob + gw0);
        __stcs(s2 + 0, make_float2(sv[0], sv[1]));
        __stcs(s2 + 1, make_float2(sv[2], sv[3]));
        // cos: offset NWIN (odd) -> streaming scalar stores
        float* cp = out + ob + NWIN + gw0;
        __stcs(cp + 0, cv[0]); __stcs(cp + 1, cv[1]);
        __stcs(cp + 2, cv[2]); __stcs(cp + 3, cv[3]);
    } else {
        #pragma unroll
        for (int w = 0; w < W; w++) {
            if (gw0 + w < NWIN) {
                __stcs(out + ob + gw0 + w,        sv[w]);
                __stcs(out + ob + NWIN + gw0 + w, cv[w]);
            }
        }
    }

    // first_three: 9 floats per batch appended after all angle rows.
    if (chunk == 0 && threadIdx.x < 9) {
        out[(long long)B_SZ * OUT_STRIDE + (long long)batch * 9 + threadIdx.x] =
            in[rowBase + threadIdx.x];
    }
}

extern "C" void kernel_launch(void* const* d_in, const int* in_sizes, int n_in,
                              void* d_out, int out_size) {
    const float* in = (const float*)d_in[0];
    float* out = (float*)d_out;
    dihedral_kernel<<<B_SZ * CHUNKS, TPB>>>(in, out);
}

// round 17
// speedup vs baseline: 1.0784x; 1.0069x over previous
#include <cuda_runtime.h>
#include <cuda_bf16.h>
#include <cstdint>

// CartesianToDihedral: (1024, 2048, 3, 3) f32 -> (angles (1024,12282), first_three (1024,9))
// Consolidated best: W=4, TPB=128 (finer drain, same 64 warps/SM), 3x LDG.128 owned
// floats, edge shuffles (E4=E0', E5=E1', p4=p0'), hoisted lane-31 overlap loads,
// PLAIN stores (stcs showed no benefit), scale-invariant core:
//   atan2(yc, xc) == atan2(-L*(e0 . (b x e2)), (e0 x b).(b x e2) + 1e-8*s)
// with b = e1+eps, s = b.b > 0, L = sqrt(s). Exact (positive-scale invariance).

namespace {
constexpr int B_SZ        = 1024;
constexpr int PTS_PER_ROW = 6144;                 // 2048*3
constexpr int FLT_PER_ROW = PTS_PER_ROW * 3;      // 18432
constexpr int NWIN        = PTS_PER_ROW - 3;      // 6141
constexpr int OUT_STRIDE  = 2 * NWIN;             // 12282
constexpr int W           = 4;                    // windows per thread
constexpr int TPB         = 128;
constexpr int WIN_PER_BLK = W * TPB;              // 512
constexpr int CHUNKS      = 12;                   // 12*512 = 6144 >= 6141
constexpr long long TOTAL_IN = (long long)B_SZ * FLT_PER_ROW;  // 18,874,368
}

__device__ __forceinline__ void dihedral_core(
    float e0x, float e0y, float e0z,
    float e1x, float e1y, float e1z,
    float e2x, float e2y, float e2z,
    float& sv, float& cv)
{
    // b = e1 + 1e-8 (unnormalized)
    const float bx = e1x + 1e-8f;
    const float by = e1y + 1e-8f;
    const float bz = e1z + 1e-8f;
    const float s  = fmaf(bx, bx, fmaf(by, by, bz * bz));   // |b|^2 > 0

    // n1 = cross(e0, b)
    const float n1x = fmaf(e0y, bz, -e0z * by);
    const float n1y = fmaf(e0z, bx, -e0x * bz);
    const float n1z = fmaf(e0x, by, -e0y * bx);
    // n2 = cross(b, e2)
    const float n2x = fmaf(by, e2z, -bz * e2y);
    const float n2y = fmaf(bz, e2x, -bx * e2z);
    const float n2z = fmaf(bx, e2y, -by * e2x);

    // xc = n1.n2 + 1e-8*s ; yc = -sqrt(s) * (e0.n2)
    const float xc = fmaf(n1x, n2x, fmaf(n1y, n2y, fmaf(n1z, n2z, 1e-8f * s)));
    const float d  = fmaf(e0x, n2x, fmaf(e0y, n2y, e0z * n2z));
    const float t  = -sqrtf(s) * d;

    const float r2 = fmaf(xc, xc, t * t);   // > 0 always
    const float ri = rsqrtf(r2);
    sv = t * ri;
    cv = xc * ri;
}

__global__ __launch_bounds__(TPB)
void dihedral_kernel(const float* __restrict__ in, float* __restrict__ out) {
    const int bid   = blockIdx.x;
    const int batch = bid / CHUNKS;
    const int chunk = bid - batch * CHUNKS;
    const int lane  = threadIdx.x & 31;
    const bool last = (lane == 31);
    const int gw0   = chunk * WIN_PER_BLK + threadIdx.x * W;

    const long long rowBase = (long long)batch * FLT_PER_ROW;
    const long long fbase   = rowBase + (long long)gw0 * 3;   // mult of 12 -> 16B aligned

    // ── Owned floats f[0..11]: 3 aligned LDG.128. Always in bounds.
    float f[12];
    {
        const float4* p4p = reinterpret_cast<const float4*>(in + fbase);
        const float4 v0 = p4p[0], v1 = p4p[1], v2 = p4p[2];
        f[0]=v0.x; f[1]=v0.y; f[2]=v0.z;  f[3]=v0.w;
        f[4]=v1.x; f[5]=v1.y; f[6]=v1.z;  f[7]=v1.w;
        f[8]=v2.x; f[9]=v2.y; f[10]=v2.z; f[11]=v2.w;
    }

    // ── Hoisted predicated overlap loads (lane 31 only): MLP with the f loads.
    float g[9];
    if (last) {
        const long long gbase = fbase + 12;          // 16B aligned
        if (gbase + 9 <= TOTAL_IN) {                 // false only at global tail
            const float4 v0 = *reinterpret_cast<const float4*>(in + gbase);
            const float4 v1 = *reinterpret_cast<const float4*>(in + gbase + 4);
            g[0]=v0.x; g[1]=v0.y; g[2]=v0.z; g[3]=v0.w;
            g[4]=v1.x; g[5]=v1.y; g[6]=v1.z; g[7]=v1.w;
            g[8] = in[gbase + 8];
        } else {
            #pragma unroll
            for (int j = 0; j < 9; j++)
                g[j] = (gbase + j < TOTAL_IN) ? in[gbase + j] : 0.0f;
        }
    }

    // ── Owned edges E_j = p_j - p_{j+1}, j = 0..2.
    const float E0x = f[0]-f[3],  E0y = f[1]-f[4],  E0z = f[2]-f[5];
    const float E1x = f[3]-f[6],  E1y = f[4]-f[7],  E1z = f[5]-f[8];
    const float E2x = f[6]-f[9],  E2y = f[7]-f[10], E2z = f[8]-f[11];

    // ── Neighbor data via shuffle: p4 = p0'; E4 = E0'; E5 = E1'.
    float p4x = __shfl_down_sync(0xFFFFFFFFu, f[0], 1);
    float p4y = __shfl_down_sync(0xFFFFFFFFu, f[1], 1);
    float p4z = __shfl_down_sync(0xFFFFFFFFu, f[2], 1);
    float E4x = __shfl_down_sync(0xFFFFFFFFu, E0x, 1);
    float E4y = __shfl_down_sync(0xFFFFFFFFu, E0y, 1);
    float E4z = __shfl_down_sync(0xFFFFFFFFu, E0z, 1);
    float E5x = __shfl_down_sync(0xFFFFFFFFu, E1x, 1);
    float E5y = __shfl_down_sync(0xFFFFFFFFu, E1y, 1);
    float E5z = __shfl_down_sync(0xFFFFFFFFu, E1z, 1);
    if (last) {
        p4x = g[0]; p4y = g[1]; p4z = g[2];
        E4x = g[0]-g[3]; E4y = g[1]-g[4]; E4z = g[2]-g[5];
        E5x = g[3]-g[6]; E5y = g[4]-g[7]; E5z = g[5]-g[8];
    }
    const float E3x = f[9]-p4x, E3y = f[10]-p4y, E3z = f[11]-p4z;

    float sv[W], cv[W];
    dihedral_core(E0x,E0y,E0z, E1x,E1y,E1z, E2x,E2y,E2z, sv[0], cv[0]);
    dihedral_core(E1x,E1y,E1z, E2x,E2y,E2z, E3x,E3y,E3z, sv[1], cv[1]);
    dihedral_core(E2x,E2y,E2z, E3x,E3y,E3z, E4x,E4y,E4z, sv[2], cv[2]);
    dihedral_core(E3x,E3y,E3z, E4x,E4y,E4z, E5x,E5y,E5z, sv[3], cv[3]);

    const long long ob = (long long)batch * OUT_STRIDE;

    if (gw0 + W <= NWIN) {
        // sin: (ob+gw0) even -> 8B-aligned float2 stores
        float2* s2 = reinterpret_cast<float2*>(out + ob + gw0);
        s2[0] = make_float2(sv[0], sv[1]);
        s2[1] = make_float2(sv[2], sv[3]);
        // cos: offset NWIN (odd) -> scalar stores (warp-contiguous)
        float* cp = out + ob + NWIN + gw0;
        cp[0] = cv[0]; cp[1] = cv[1]; cp[2] = cv[2]; cp[3] = cv[3];
    } else {
        #pragma unroll
        for (int w = 0; w < W; w++) {
            if (gw0 + w < NWIN) {
                out[ob + gw0 + w]        = sv[w];
                out[ob + NWIN + gw0 + w] = cv[w];
            }
        }
    }

    // first_three: 9 floats per batch appended after all angle rows.
    if (chunk == 0 && threadIdx.x < 9) {
        out[(long long)B_SZ * OUT_STRIDE + (long long)batch * 9 + threadIdx.x] =
            in[rowBase + threadIdx.x];
    }
}

extern "C" void kernel_launch(void* const* d_in, const int* in_sizes, int n_in,
                              void* d_out, int out_size) {
    const float* in = (const float*)d_in[0];
    float* out = (float*)d_out;
    dihedral_kernel<<<B_SZ * CHUNKS, TPB>>>(in, out);
}